// round 2
// baseline (speedup 1.0000x reference)
#include <cuda_runtime.h>
#include <cstdint>

#define B_   32
#define H_   512
#define N_   1000
#define KTOT 2560   // 5*H concatenated contraction dim
#define G4   2048   // 4*H gates

// ---------------- device scratch (static: no allocations) ----------------
__device__ float g_Wcat[H_ * KTOT];   // [o][k], tf32-rounded weights (5.24 MB, L2-resident)
__device__ float g_gates[B_ * G4];
__device__ float g_qplus[B_ * H_];    // q[b,o] + bq + bd + bdr + bdist + bchl + bref

__device__ __forceinline__ float to_tf32(float x) {
    uint32_t u;
    asm("cvt.rna.tf32.f32 %0, %1;" : "=r"(u) : "f"(x));
    return __uint_as_float(u);
}

// ---------------- K0: pack + round weights into concat layout ----------------
__global__ void k_pack(const float* __restrict__ Wd, const float* __restrict__ Wdr,
                       const float* __restrict__ Wdist, const float* __restrict__ Wchl,
                       const float* __restrict__ Wref) {
    int idx = blockIdx.x * blockDim.x + threadIdx.x;
    if (idx >= H_ * KTOT) return;
    int o = idx / KTOT, k = idx - o * KTOT;
    int i = k >> 9, h = k & 511;
    const float* W = (i == 0) ? Wd : (i == 1) ? Wdr : (i == 2) ? Wdist : (i == 3) ? Wchl : Wref;
    g_Wcat[idx] = to_tf32(W[o * H_ + h]);
}

// ---------------- K1: LSTM gates (exact fp32) ----------------
// grid (2048/64, 32/8) = (32,4); 256 thr; block: 64 gate-rows x 8 batches
__global__ void k_gates(const float* __restrict__ dec, const float* __restrict__ h0,
                        const float* __restrict__ Wih, const float* __restrict__ Whh) {
    __shared__ float xs[8][H_];
    __shared__ float hs[8][H_];
    int t = threadIdx.x;
    int b0 = blockIdx.y * 8;
    for (int i = t; i < 8 * H_; i += 256) {
        int bb = i >> 9, k = i & 511;
        xs[bb][k] = dec[(b0 + bb) * H_ + k];   // decoder_input[:,:,0]
        hs[bb][k] = h0[(b0 + bb) * H_ + k];
    }
    __syncthreads();
    int j = blockIdx.x * 64 + (t >> 2);
    int part = t & 3;
    float acc[8];
#pragma unroll
    for (int bb = 0; bb < 8; ++bb) acc[bb] = 0.f;
    const float* wi = Wih + (size_t)j * H_;
    const float* wh = Whh + (size_t)j * H_;
    for (int tt = 0; tt < 128; ++tt) {
        int k = part + (tt << 2);
        float a = wi[k], c = wh[k];
#pragma unroll
        for (int bb = 0; bb < 8; ++bb) acc[bb] += xs[bb][k] * a + hs[bb][k] * c;
    }
#pragma unroll
    for (int bb = 0; bb < 8; ++bb) {
        acc[bb] += __shfl_xor_sync(0xffffffffu, acc[bb], 1);
        acc[bb] += __shfl_xor_sync(0xffffffffu, acc[bb], 2);
    }
    if (part == 0) {
#pragma unroll
        for (int bb = 0; bb < 8; ++bb) g_gates[(b0 + bb) * G4 + j] = acc[bb];
    }
}

// ---------------- K1b: LSTM cell pointwise, writes h_new/c_new into d_out ----------------
__global__ void k_cell(const float* __restrict__ c0, float* __restrict__ out) {
    int idx = blockIdx.x * blockDim.x + threadIdx.x;
    if (idx >= B_ * H_) return;
    int b = idx >> 9, j = idx & 511;
    const float* g = g_gates + b * G4;
    float ig = g[j], fg = g[H_ + j], gg = g[2 * H_ + j], og = g[3 * H_ + j];
    float si = 1.f / (1.f + expf(-ig));
    float sf = 1.f / (1.f + expf(-fg));
    float so = 1.f / (1.f + expf(-og));
    float cn = sf * c0[idx] + si * tanhf(gg);
    float hn = so * tanhf(cn);
    out[B_ * N_ + idx]           = hn;   // h_new at float offset 32000
    out[B_ * N_ + B_ * H_ + idx] = cn;   // c_new at 32000+16384
}

// ---------------- K2: qplus[b,o] = h_new @ Wq^T + (bq + sum of conv biases) ----------------
// grid (512/64, 32/8) = (8,4); 256 thr
__global__ void k_qplus(const float* __restrict__ out, const float* __restrict__ Wq,
                        const float* __restrict__ bq, const float* __restrict__ bd,
                        const float* __restrict__ bdr, const float* __restrict__ bdist,
                        const float* __restrict__ bchl, const float* __restrict__ bref) {
    __shared__ float hs[8][H_];
    int t = threadIdx.x;
    int b0 = blockIdx.y * 8;
    const float* hnew = out + B_ * N_;
    for (int i = t; i < 8 * H_; i += 256) {
        int bb = i >> 9, k = i & 511;
        hs[bb][k] = hnew[(b0 + bb) * H_ + k];
    }
    __syncthreads();
    int o = blockIdx.x * 64 + (t >> 2);
    int part = t & 3;
    float acc[8];
#pragma unroll
    for (int bb = 0; bb < 8; ++bb) acc[bb] = 0.f;
    const float* w = Wq + (size_t)o * H_;
    for (int tt = 0; tt < 128; ++tt) {
        int k = part + (tt << 2);
        float a = w[k];
#pragma unroll
        for (int bb = 0; bb < 8; ++bb) acc[bb] += hs[bb][k] * a;
    }
#pragma unroll
    for (int bb = 0; bb < 8; ++bb) {
        acc[bb] += __shfl_xor_sync(0xffffffffu, acc[bb], 1);
        acc[bb] += __shfl_xor_sync(0xffffffffu, acc[bb], 2);
    }
    if (part == 0) {
        float bias = bq[o] + bd[o] + bdr[o] + bdist[o] + bchl[o] + bref[o];
#pragma unroll
        for (int bb = 0; bb < 8; ++bb) g_qplus[(b0 + bb) * H_ + o] = acc[bb] + bias;
    }
}

// ---------------- K3: fused 5-way conv GEMM (tf32 mma.sync) + tanh + v-reduce ----------------
#define BM 128
#define BN 128
#define BK 32
#define AS_LD 36     // 36 mod 32 == 4  -> conflict-free A frag loads
#define BS_LD 136    // 136 mod 32 == 8 -> conflict-free B frag loads
#define NCH (KTOT / BK)   // 80

__global__ __launch_bounds__(256)
void k_main(const float* __restrict__ x0, const float* __restrict__ x1,
            const float* __restrict__ x2, const float* __restrict__ x3,
            const float* __restrict__ x4,
            const float* __restrict__ v, float* __restrict__ out) {
    extern __shared__ float smem[];
    float* As = smem;                      // 2 * BM * AS_LD
    float* Bs = smem + 2 * BM * AS_LD;     // 2 * BK * BS_LD

    const int t = threadIdx.x;
    const int warp = t >> 5, lane = t & 31;
    const int wm = warp >> 2, wn = warp & 3;     // 2 x 4 warp grid, warp tile 64x32
    const int g = lane >> 2, tg = lane & 3;
    const int mtile = blockIdx.x, ntile = blockIdx.y, b = blockIdx.z;

    const float* xs[5] = {x0, x1, x2, x3, x4};   // k-order: d, d_rem, dist, ch_l, static_hidden

    // gmem staging maps
    const int a_o = t >> 1;
    const int a_k = (t & 1) * 4;                 // + j*8 -> covers k 0..31
    const float* aBase = g_Wcat + (size_t)(mtile * BM + a_o) * KTOT + a_k;
    const int b_k = t >> 3;
    const int b_n = (t & 7) * 16;                // + u*4 -> covers n 0..127
    const int n0 = ntile * BN;

    float4 aR[4], bR[4];
    float acc[4][4][4];
#pragma unroll
    for (int i = 0; i < 4; ++i)
#pragma unroll
        for (int j = 0; j < 4; ++j)
#pragma unroll
            for (int c = 0; c < 4; ++c) acc[i][j][c] = 0.f;

    auto loadA = [&](int ch) {
#pragma unroll
        for (int j = 0; j < 4; ++j) aR[j] = *(const float4*)(aBase + ch * BK + j * 8);
    };
    auto loadB = [&](int ch) {
        int k = ch * BK + b_k;                   // chunk never crosses a 512 boundary
        const float* xp = xs[k >> 9] + (size_t)b * (H_ * N_) + (size_t)(k & 511) * N_ + n0 + b_n;
#pragma unroll
        for (int u = 0; u < 4; ++u) {
            int n = n0 + b_n + u * 4;
            bR[u] = (n < N_) ? *(const float4*)(xp + u * 4) : make_float4(0.f, 0.f, 0.f, 0.f);
        }
    };
    auto storeA = [&](int buf) {
        float* dst = As + buf * BM * AS_LD + a_o * AS_LD + a_k;
#pragma unroll
        for (int j = 0; j < 4; ++j) *(float4*)(dst + j * 8) = aR[j];   // already tf32-rounded
    };
    auto storeB = [&](int buf) {
        float* dst = Bs + buf * BK * BS_LD + b_k * BS_LD + b_n;
#pragma unroll
        for (int u = 0; u < 4; ++u) {
            float4 val = bR[u];
            val.x = to_tf32(val.x); val.y = to_tf32(val.y);
            val.z = to_tf32(val.z); val.w = to_tf32(val.w);
            *(float4*)(dst + u * 4) = val;
        }
    };
    auto compute = [&](int buf) {
        const float* A = As + buf * BM * AS_LD;
        const float* Bsm = Bs + buf * BK * BS_LD;
#pragma unroll
        for (int ks = 0; ks < 4; ++ks) {
            uint32_t af[4][4], bf[4][2];
#pragma unroll
            for (int mi = 0; mi < 4; ++mi) {
                int row = wm * 64 + mi * 16 + g;
                int col = ks * 8 + tg;
                af[mi][0] = __float_as_uint(A[row * AS_LD + col]);
                af[mi][1] = __float_as_uint(A[(row + 8) * AS_LD + col]);
                af[mi][2] = __float_as_uint(A[row * AS_LD + col + 4]);
                af[mi][3] = __float_as_uint(A[(row + 8) * AS_LD + col + 4]);
            }
#pragma unroll
            for (int ni = 0; ni < 4; ++ni) {
                int coln = wn * 32 + ni * 8 + g;
                bf[ni][0] = __float_as_uint(Bsm[(ks * 8 + tg) * BS_LD + coln]);
                bf[ni][1] = __float_as_uint(Bsm[(ks * 8 + 4 + tg) * BS_LD + coln]);
            }
#pragma unroll
            for (int mi = 0; mi < 4; ++mi)
#pragma unroll
                for (int ni = 0; ni < 4; ++ni)
                    asm volatile(
                        "mma.sync.aligned.m16n8k8.row.col.f32.tf32.tf32.f32 "
                        "{%0,%1,%2,%3}, {%4,%5,%6,%7}, {%8,%9}, {%0,%1,%2,%3};\n"
                        : "+f"(acc[mi][ni][0]), "+f"(acc[mi][ni][1]),
                          "+f"(acc[mi][ni][2]), "+f"(acc[mi][ni][3])
                        : "r"(af[mi][0]), "r"(af[mi][1]), "r"(af[mi][2]), "r"(af[mi][3]),
                          "r"(bf[ni][0]), "r"(bf[ni][1]));
        }
    };

    loadA(0); loadB(0);
    storeA(0); storeB(0);
    __syncthreads();
#pragma unroll 1
    for (int ch = 0; ch < NCH; ++ch) {
        if (ch + 1 < NCH) { loadA(ch + 1); loadB(ch + 1); }
        compute(ch & 1);
        if (ch + 1 < NCH) {
            storeA((ch + 1) & 1);
            storeB((ch + 1) & 1);
            __syncthreads();
        }
    }

    // ---- fused epilogue: t = tanh(Y + qplus), partial logits = sum_o v[o]*t ----
    __syncthreads();
    float* spart = smem;   // reuse As region, 128 floats
    float p[4][2];
#pragma unroll
    for (int ni = 0; ni < 4; ++ni) { p[ni][0] = 0.f; p[ni][1] = 0.f; }
    const float* qp = g_qplus + b * H_;
#pragma unroll
    for (int mi = 0; mi < 4; ++mi) {
        int o0 = mtile * BM + wm * 64 + mi * 16 + g;
        float q0 = qp[o0], q1 = qp[o0 + 8];
        float v0 = v[o0], v1 = v[o0 + 8];
#pragma unroll
        for (int ni = 0; ni < 4; ++ni) {
            p[ni][0] += v0 * tanhf(acc[mi][ni][0] + q0) + v1 * tanhf(acc[mi][ni][2] + q1);
            p[ni][1] += v0 * tanhf(acc[mi][ni][1] + q0) + v1 * tanhf(acc[mi][ni][3] + q1);
        }
    }
#pragma unroll
    for (int ni = 0; ni < 4; ++ni)
#pragma unroll
        for (int j = 0; j < 2; ++j) {
            p[ni][j] += __shfl_xor_sync(0xffffffffu, p[ni][j], 4);
            p[ni][j] += __shfl_xor_sync(0xffffffffu, p[ni][j], 8);
            p[ni][j] += __shfl_xor_sync(0xffffffffu, p[ni][j], 16);
        }
    if (wm == 0 && g == 0) {
#pragma unroll
        for (int ni = 0; ni < 4; ++ni) {
            spart[wn * 32 + ni * 8 + 2 * tg + 0] = p[ni][0];
            spart[wn * 32 + ni * 8 + 2 * tg + 1] = p[ni][1];
        }
    }
    __syncthreads();
    if (wm == 1 && g == 0) {
#pragma unroll
        for (int ni = 0; ni < 4; ++ni) {
            spart[wn * 32 + ni * 8 + 2 * tg + 0] += p[ni][0];
            spart[wn * 32 + ni * 8 + 2 * tg + 1] += p[ni][1];
        }
    }
    __syncthreads();
    if (t < BN) {
        int n = ntile * BN + t;
        if (n < N_) atomicAdd(out + b * N_ + n, spart[t]);
    }
}

// ---------------- launch ----------------
extern "C" void kernel_launch(void* const* d_in, const int* in_sizes, int n_in,
                              void* d_out, int out_size) {
    const float* static_hidden = (const float*)d_in[0];
    const float* static_ch_l   = (const float*)d_in[1];
    const float* d             = (const float*)d_in[2];
    const float* d_rem         = (const float*)d_in[3];
    const float* dist          = (const float*)d_in[4];
    const float* dec           = (const float*)d_in[5];
    const float* h0            = (const float*)d_in[6];
    const float* c0            = (const float*)d_in[7];
    const float* Wih           = (const float*)d_in[8];
    const float* Whh           = (const float*)d_in[9];
    const float* Wd            = (const float*)d_in[10];
    const float* bd            = (const float*)d_in[11];
    const float* Wdr           = (const float*)d_in[12];
    const float* bdr           = (const float*)d_in[13];
    const float* Wdist         = (const float*)d_in[14];
    const float* bdist         = (const float*)d_in[15];
    const float* Wchl          = (const float*)d_in[16];
    const float* bchl          = (const float*)d_in[17];
    const float* Wref          = (const float*)d_in[18];
    const float* bref          = (const float*)d_in[19];
    const float* Wq            = (const float*)d_in[20];
    const float* bq            = (const float*)d_in[21];
    const float* v             = (const float*)d_in[22];
    float* out = (float*)d_out;

    // zero the logits region (atomicAdd target); h/c regions are fully overwritten
    cudaMemsetAsync(out, 0, B_ * N_ * sizeof(float), 0);

    k_pack<<<(H_ * KTOT + 255) / 256, 256>>>(Wd, Wdr, Wdist, Wchl, Wref);
    k_gates<<<dim3(G4 / 64, B_ / 8), 256>>>(dec, h0, Wih, Whh);
    k_cell<<<(B_ * H_ + 255) / 256, 256>>>(c0, out);
    k_qplus<<<dim3(H_ / 64, B_ / 8), 256>>>(out, Wq, bq, bd, bdr, bdist, bchl, bref);

    int smem_bytes = (2 * BM * AS_LD + 2 * BK * BS_LD) * (int)sizeof(float);  // ~70 KB
    cudaFuncSetAttribute(k_main, cudaFuncAttributeMaxDynamicSharedMemorySize, smem_bytes);
    k_main<<<dim3(4, 8, B_), 256, smem_bytes>>>(d, d_rem, dist, static_ch_l, static_hidden, v, out);
}